// round 5
// baseline (speedup 1.0000x reference)
#include <cuda_runtime.h>
#include <cstdint>

// Problem constants
#define NB   32
#define NS   128
#define NW   4096      // NB*NS independent words
#define CC   32        // chars per word (time steps)
#define HH   256       // hidden
#define G3   768       // 3*H
#define EE   128       // embed dim
#define NV   262       // vocab
#define WPB  16        // words per block
#define HROW 20        // padded smem row for h (16 words + pad, 16B aligned)

#define CHUNK_K      8                        // k-values per weight chunk
#define NCHUNK       (HH / CHUNK_K)           // 32 chunks per step
#define TOTAL_CHUNKS (CC * NCHUNK)            // 1024
#define CHUNK_FLOATS (CHUNK_K * G3)           // 6144
#define CHUNK_BYTES  (CHUNK_FLOATS * 4)       // 24576
#define HALF_FLOATS  (CHUNK_FLOATS / 2)       // 3072
#define HALF_BYTES   (CHUNK_BYTES / 2)        // 12288

// dynamic smem layout (bytes)
#define BAR_OFF   0                            // 4 x u64 mbarriers
#define H_OFF     128
#define W_OFF     (H_OFF + HH * HROW * 4)      // 20608
#define SMEM_TOTAL (W_OFF + 2 * CHUNK_BYTES)   // 69760

typedef unsigned long long u64;

// Precomputed x-projection table: P[d][v][j] = embed[v].W_ih[d][j] + b_ih[d][j]
// (+ b_hh[j] folded in for the r and z gates, j < 512)
__device__ float g_P[2][NV][G3];
// k-major transposed recurrent weights: g_Wt[d][k][j] = W_hh[d][j][k]
__device__ float g_Wt[2][HH][G3];
// k-major transposed input weights (for coalesced prep_p)
__device__ float g_WtI[2][EE][G3];

// ---------------------------------------------------------------------------
// Packed fp32x2 helpers (Blackwell 2x-rate fp32; ptxas never auto-emits)
// ---------------------------------------------------------------------------
__device__ __forceinline__ void fma2(u64& d, u64 a, u64 b) {
    asm("fma.rn.f32x2 %0, %1, %2, %3;" : "=l"(d) : "l"(a), "l"(b), "l"(d));
}
__device__ __forceinline__ u64 dup2(float x) {
    u64 r;
    asm("mov.b64 %0, {%1, %1};" : "=l"(r) : "f"(x));
    return r;
}

// ---------------------------------------------------------------------------
// mbarrier / cluster helpers
// ---------------------------------------------------------------------------
__device__ __forceinline__ uint32_t smem_u32(const void* p) {
    uint32_t a;
    asm("{ .reg .u64 t; cvta.to.shared.u64 t, %1; cvt.u32.u64 %0, t; }"
        : "=r"(a) : "l"(p));
    return a;
}
__device__ __forceinline__ uint32_t ctarank() {
    uint32_t r; asm("mov.u32 %0, %%cluster_ctarank;" : "=r"(r)); return r;
}
#define MBAR_INIT(a, cnt) \
    asm volatile("mbarrier.init.shared.b64 [%0], %1;" \
                 :: "r"(a), "r"((uint32_t)(cnt)) : "memory")
#define MBAR_EXPECT_TX(a, bytes) \
    asm volatile("mbarrier.arrive.expect_tx.shared.b64 _, [%0], %1;" \
                 :: "r"(a), "r"((uint32_t)(bytes)) : "memory")
#define MBAR_ARRIVE_CLUSTER(a, rk) \
    asm volatile("{ .reg .b32 ra; mapa.shared::cluster.u32 ra, %0, %1; " \
                 "mbarrier.arrive.shared::cluster.b64 _, [ra]; }" \
                 :: "r"(a), "r"((uint32_t)(rk)) : "memory")
#define MBAR_WAIT(a, par) do {                                               \
    uint32_t _done;                                                          \
    asm volatile("{ .reg .pred p; "                                          \
        "mbarrier.try_wait.parity.acquire.cta.shared::cta.b64 p, [%1], %2; " \
        "selp.b32 %0, 1, 0, p; }"                                            \
        : "=r"(_done) : "r"(a), "r"((uint32_t)(par)) : "memory");            \
    while (!_done) {                                                         \
        asm volatile("{ .reg .pred p; "                                      \
            "mbarrier.try_wait.parity.acquire.cta.shared::cta.b64 p, [%1], %2, 0x989680; " \
            "selp.b32 %0, 1, 0, p; }"                                        \
            : "=r"(_done) : "r"(a), "r"((uint32_t)(par)) : "memory");        \
    } } while (0)
#define CLUSTER_SYNC_() do { \
    asm volatile("barrier.cluster.arrive.aligned;" ::: "memory"); \
    asm volatile("barrier.cluster.wait.aligned;"   ::: "memory"); } while (0)
// bulk async copy global -> shared, multicast to cluster CTAs in mask
#define BULK_MC(dst, src, bytes, mbar, mask) \
    asm volatile("cp.async.bulk.shared::cluster.global.mbarrier::complete_tx::bytes" \
                 ".multicast::cluster [%0], [%1], %2, [%3], %4;" \
                 :: "r"(dst), "l"(src), "r"((uint32_t)(bytes)), "r"(mbar), \
                    "h"((uint16_t)(mask)) : "memory")

// ---------------------------------------------------------------------------
// Prepack 0: transpose W_hh (768x256) and W_ih (768x128) to k-major.
// ---------------------------------------------------------------------------
__global__ void prep_tr_kernel(const float* __restrict__ Whh_fw,
                               const float* __restrict__ Whh_bw,
                               const float* __restrict__ Wih_fw,
                               const float* __restrict__ Wih_bw)
{
    int j = blockIdx.x;
    int d = blockIdx.y;
    int k = threadIdx.x;
    const float* Wh = d ? Whh_bw : Whh_fw;
    const float* Wi = d ? Wih_bw : Wih_fw;
    g_Wt[d][k][j] = Wh[(size_t)j * HH + k];
    if (k < EE) g_WtI[d][k][j] = Wi[(size_t)j * EE + k];
}

// ---------------------------------------------------------------------------
// Prepack 1: input-projection table, coalesced via g_WtI.  grid (NV, 2).
// ---------------------------------------------------------------------------
__global__ void prep_p_kernel(const float* __restrict__ embed,
                              const float* __restrict__ bih_fw,
                              const float* __restrict__ bhh_fw,
                              const float* __restrict__ bih_bw,
                              const float* __restrict__ bhh_bw)
{
    int v = blockIdx.x;
    int d = blockIdx.y;
    int tid = threadIdx.x;
    const float* bi = d ? bih_bw : bih_fw;
    const float* bh = d ? bhh_bw : bhh_fw;
    const float* ev = embed + (size_t)v * EE;
    float a0 = 0.f, a1 = 0.f, a2 = 0.f;
#pragma unroll 4
    for (int k = 0; k < EE; k++) {
        float e = __ldg(ev + k);                        // warp-broadcast
        const float* w = &g_WtI[d][k][0];
        a0 = fmaf(e, __ldg(w + tid),       a0);
        a1 = fmaf(e, __ldg(w + tid + 256), a1);
        a2 = fmaf(e, __ldg(w + tid + 512), a2);
    }
    g_P[d][v][tid]       = a0 + bi[tid]       + bh[tid];
    g_P[d][v][tid + 256] = a1 + bi[tid + 256] + bh[tid + 256];
    g_P[d][v][tid + 512] = a2 + bi[tid + 512];          // n-gate: b_hh NOT folded
}

// ---------------------------------------------------------------------------
// Activations
// ---------------------------------------------------------------------------
__device__ __forceinline__ float sigmoid_f(float x) {
    return __fdividef(1.f, 1.f + __expf(-x));
}
__device__ __forceinline__ float tanh_f(float x) {
    x = fmaxf(-15.f, fminf(15.f, x));
    float e = __expf(-2.f * x);
    return __fdividef(1.f - e, 1.f + e);
}

// ---------------------------------------------------------------------------
// Main recurrent kernel: packed fp32x2 + cluster-2 multicast weight stream.
// Cluster = 2 same-direction CTAs sharing one weight fetch via bulk-multicast
// into a double-buffered smem chunk ring (8 k per 24KB chunk).  Thread tid
// owns the (r,z,n) gate triple for hidden index i = tid; words packed in
// pairs into f32x2 lanes; h stored word-major per k in smem.
// ---------------------------------------------------------------------------
extern __shared__ char smem_dyn[];

__global__ void __launch_bounds__(256, 2) __cluster_dims__(2, 1, 1)
gru_kernel(const int*   __restrict__ chars,       // [NW, CC]
           const int*   __restrict__ chars_mask,  // [NW, CC]
           const int*   __restrict__ data_mask,   // [NW]
           const float* __restrict__ bhh_fw,      // [G3]
           const float* __restrict__ bhh_bw,
           float*       __restrict__ out)         // [NW, 512]
{
    float* hsm  = reinterpret_cast<float*>(smem_dyn + H_OFF);   // h[k][word]
    float* wbuf = reinterpret_cast<float*>(smem_dyn + W_OFF);   // [2][8][768]
    const uint32_t bar0  = smem_u32(smem_dyn);       // full0@+0 full1@+8
    const uint32_t wbase = smem_u32(wbuf);           // empty0@+16 empty1@+24

    const int tid  = threadIdx.x;
    const uint32_t rank = ctarank();
    const int c  = blockIdx.x >> 1;                  // cluster id
    const int d  = c & 1;                            // direction (same per pair)
    const int n0 = (((c >> 1) << 1) + (int)rank) * WPB;

    const float* __restrict__ Wd = &g_Wt[d][0][0];
    const float  bn = (d ? bhh_bw : bhh_fw)[tid + 512];

    if (tid == 0) {
        MBAR_INIT(bar0 + 0, 1);    // full[0]  (1 expect_tx arrive)
        MBAR_INIT(bar0 + 8, 1);    // full[1]
        MBAR_INIT(bar0 + 16, 2);   // empty[0] (one arrive per CTA)
        MBAR_INIT(bar0 + 24, 2);   // empty[1]
    }
    // init h = 0
#pragma unroll
    for (int q = 0; q < HH * HROW / 256; q++)
        hsm[tid + q * 256] = 0.f;
    __syncthreads();
    CLUSTER_SYNC_();               // peer barriers visible before multicast

    // prime chunks 0 and 1
    if (tid == 0) {
#pragma unroll
        for (int gc = 0; gc < 2; gc++) {
            uint32_t fb = bar0 + 8 * gc;
            MBAR_EXPECT_TX(fb, CHUNK_BYTES);
            const float* src = Wd + (size_t)gc * CHUNK_FLOATS + rank * HALF_FLOATS;
            uint32_t dst = wbase + gc * CHUNK_BYTES + rank * HALF_BYTES;
            BULK_MC(dst, src, HALF_BYTES, fb, 0x3);
        }
    }

    for (int step = 0; step < CC; step++) {
        const int t = d ? (CC - 1 - step) : step;

        u64 accr[WPB / 2], accz[WPB / 2], accn[WPB / 2];
#pragma unroll
        for (int p = 0; p < WPB / 2; p++) { accr[p] = 0ull; accz[p] = 0ull; accn[p] = 0ull; }

        for (int s = 0; s < NCHUNK; s++) {
            const int gc = step * NCHUNK + s;
            const int b  = gc & 1;
            const uint32_t fb = bar0 + 8 * b;
            MBAR_WAIT(fb, (uint32_t)((gc >> 1) & 1));   // weights landed

            const float* __restrict__ wb = wbuf + b * CHUNK_FLOATS;
#pragma unroll
            for (int i = 0; i < CHUNK_K; i++) {
                const int k = s * CHUNK_K + i;
                const u64 wr2 = dup2(wb[i * G3 + tid]);
                const u64 wz2 = dup2(wb[i * G3 + tid + 256]);
                const u64 wn2 = dup2(wb[i * G3 + tid + 512]);
                const ulonglong2* __restrict__ hk =
                    reinterpret_cast<const ulonglong2*>(&hsm[k * HROW]);
#pragma unroll
                for (int q = 0; q < WPB / 4; q++) {      // 4 LDS.128 broadcast
                    ulonglong2 a = hk[q];                // words 4q..4q+3
                    fma2(accr[2 * q],     a.x, wr2);
                    fma2(accz[2 * q],     a.x, wz2);
                    fma2(accn[2 * q],     a.x, wn2);
                    fma2(accr[2 * q + 1], a.y, wr2);
                    fma2(accz[2 * q + 1], a.y, wz2);
                    fma2(accn[2 * q + 1], a.y, wn2);
                }
            }
            __syncthreads();                             // CTA done with buf b
            if (tid == 0) {
                const uint32_t eb = bar0 + 16 + 8 * b;
                MBAR_ARRIVE_CLUSTER(eb, 0);              // free buf b in both CTAs
                MBAR_ARRIVE_CLUSTER(eb, 1);
                const int gcn = gc + 2;
                if (gcn < TOTAL_CHUNKS) {
                    MBAR_WAIT(eb, (uint32_t)(((gcn >> 1) - 1) & 1));  // both freed
                    MBAR_EXPECT_TX(fb, CHUNK_BYTES);
                    const float* src = Wd + (size_t)(gcn & (NCHUNK - 1)) * CHUNK_FLOATS
                                          + rank * HALF_FLOATS;
                    uint32_t dst = wbase + b * CHUNK_BYTES + rank * HALF_BYTES;
                    BULK_MC(dst, src, HALF_BYTES, fb, 0x3);
                }
            }
        }

        // ---- gates (thread-local), update h (reads done at last chunk sync) -
        const float* ar = reinterpret_cast<const float*>(accr);
        const float* az = reinterpret_cast<const float*>(accz);
        const float* an = reinterpret_cast<const float*>(accn);
#pragma unroll
        for (int w = 0; w < WPB; w++) {
            const int n  = n0 + w;
            const int ch = chars[n * CC + t];
            const int mk = chars_mask[n * CC + t];
            const float* __restrict__ Prow = &g_P[d][ch][0];
            float xr = Prow[tid];                        // b_ih + b_hh folded
            float xz = Prow[tid + 256];
            float xn = Prow[tid + 512];                  // b_ih only
            float hold = hsm[tid * HROW + w];
            float r  = sigmoid_f(xr + ar[w]);
            float z  = sigmoid_f(xz + az[w]);
            float hn = bn + an[w];
            float nn = tanh_f(fmaf(r, hn, xn));
            float hnew = (1.f - z) * nn + z * hold;
            hsm[tid * HROW + w] = mk ? hnew : hold;      // freeze past seq end
        }
        __syncthreads();                                 // h visible next step
    }

    // ---- final write: out[n, d*256 + i] = h * data_mask[n] -----------------
#pragma unroll
    for (int w = 0; w < WPB; w++) {
        const int n = n0 + w;
        const float dm = data_mask[n] ? 1.f : 0.f;
        out[(size_t)n * 512 + d * 256 + tid] = hsm[tid * HROW + w] * dm;
    }
    CLUSTER_SYNC_();    // no CTA exits while peer multicast may target its smem
}

// ---------------------------------------------------------------------------
extern "C" void kernel_launch(void* const* d_in, const int* in_sizes, int n_in,
                              void* d_out, int out_size)
{
    const int*   chars      = (const int*)  d_in[0];
    const int*   chars_mask = (const int*)  d_in[1];
    const int*   data_mask  = (const int*)  d_in[2];
    const float* embed      = (const float*)d_in[3];
    const float* Wih_fw     = (const float*)d_in[4];
    const float* Whh_fw     = (const float*)d_in[5];
    const float* bih_fw     = (const float*)d_in[6];
    const float* bhh_fw     = (const float*)d_in[7];
    const float* Wih_bw     = (const float*)d_in[8];
    const float* Whh_bw     = (const float*)d_in[9];
    const float* bih_bw     = (const float*)d_in[10];
    const float* bhh_bw     = (const float*)d_in[11];
    float* out = (float*)d_out;

    static bool attr_done = false;
    if (!attr_done) {
        cudaFuncSetAttribute(gru_kernel,
                             cudaFuncAttributeMaxDynamicSharedMemorySize,
                             SMEM_TOTAL);
        attr_done = true;
    }

    prep_tr_kernel<<<dim3(G3, 2), HH>>>(Whh_fw, Whh_bw, Wih_fw, Wih_bw);
    prep_p_kernel<<<dim3(NV, 2), 256>>>(embed, bih_fw, bhh_fw, bih_bw, bhh_bw);
    gru_kernel<<<dim3(2 * 256, 1, 1), 256, SMEM_TOTAL>>>(
        chars, chars_mask, data_mask, bhh_fw, bhh_bw, out);
}